// round 3
// baseline (speedup 1.0000x reference)
#include <cuda_runtime.h>
#include <cuda_bf16.h>
#include <cstdint>
#include <math.h>

#define NN 50000
#define NE 500000
#define HIDF 256
#define NEG_SLOPE 0.2f

// ---------------- scratch (no allocation allowed) ----------------
__device__ __align__(256) float g_bufA[(size_t)NN * HIDF];
__device__ __align__(256) float g_bufB[(size_t)NN * HIDF];
__device__ __align__(256) float g_bufC[(size_t)NN * HIDF];
__device__ __align__(256) __nv_bfloat16 g_abf[(size_t)NN * 768];   // A' split bf16 (max K'=768)
__device__ __align__(256) __nv_bfloat16 g_wbf[(size_t)256 * 768];  // W' split bf16
__device__ __align__(256) __nv_bfloat16 g_wbf2[(size_t)256 * 768];
__device__ int g_src[NE];
__device__ int g_dst[NE];
__device__ int g_cnt[NN];
__device__ int g_rowptr[NN + 1];
__device__ int g_cursor[NN];
__device__ int g_ids[NE];   // SRC node id of CSR-sorted edge
__device__ float g_as[NN];
__device__ float g_ad[NN];
__device__ int g_is64;

// ---------------- helpers ----------------
__device__ __forceinline__ uint32_t smem_u32(const void* p) {
    uint32_t a;
    asm("{ .reg .u64 t; cvta.to.shared.u64 t, %1; cvt.u32.u64 %0, t; }" : "=r"(a) : "l"(p));
    return a;
}
__device__ __forceinline__ void cp_async16(uint32_t dst, const void* src, int sz) {
    asm volatile("cp.async.cg.shared.global [%0], [%1], 16, %2;" :: "r"(dst), "l"(src), "r"(sz) : "memory");
}
#define CP_COMMIT() asm volatile("cp.async.commit_group;" ::: "memory")
#define CP_WAIT0()  asm volatile("cp.async.wait_group 0;" ::: "memory")

__device__ __forceinline__ float lrelu(float e) { return e > 0.f ? e : NEG_SLOPE * e; }

// ---------------- edge index dtype detection + normalize ----------------
__global__ void detect_kernel(const int* __restrict__ w) {
    __shared__ int sh[256];
    int nz = 0;
    for (int i = 1 + 2 * (int)threadIdx.x; i < 1000000; i += 2 * (int)blockDim.x)
        nz += (w[i] != 0);
    sh[threadIdx.x] = nz;
    __syncthreads();
    for (int off = 128; off; off >>= 1) {
        if ((int)threadIdx.x < off) sh[threadIdx.x] += sh[threadIdx.x + off];
        __syncthreads();
    }
    if (threadIdx.x == 0) g_is64 = (sh[0] == 0) ? 1 : 0;
}

__global__ void convert_kernel(const void* __restrict__ ei) {
    int e = blockIdx.x * blockDim.x + threadIdx.x;
    if (e >= NE) return;
    if (g_is64) {
        const long long* p = (const long long*)ei;
        g_src[e] = (int)p[e];
        g_dst[e] = (int)p[NE + e];
    } else {
        const int* p = (const int*)ei;
        g_src[e] = p[e];
        g_dst[e] = p[NE + e];
    }
}

// ---------------- CSR build (sorted by dst, payload = src id) ----------------
__global__ void zero_cnt_kernel() {
    int i = blockIdx.x * blockDim.x + threadIdx.x;
    if (i < NN) g_cnt[i] = 0;
}
__global__ void count_kernel() {
    int e = blockIdx.x * blockDim.x + threadIdx.x;
    if (e < NE) atomicAdd(&g_cnt[g_dst[e]], 1);
}
__global__ void scan_kernel() {
    __shared__ int sdata[1024];
    __shared__ int base_s;
    if (threadIdx.x == 0) base_s = 0;
    __syncthreads();
    for (int start = 0; start < NN; start += 1024) {
        int i = start + (int)threadIdx.x;
        int v = (i < NN) ? g_cnt[i] : 0;
        sdata[threadIdx.x] = v;
        __syncthreads();
        for (int off = 1; off < 1024; off <<= 1) {
            int t = ((int)threadIdx.x >= off) ? sdata[threadIdx.x - off] : 0;
            __syncthreads();
            sdata[threadIdx.x] += t;
            __syncthreads();
        }
        int incl = sdata[threadIdx.x];
        int total = sdata[1023];
        int base = base_s;
        if (i < NN) g_rowptr[i] = base + incl - v;
        __syncthreads();
        if (threadIdx.x == 0) base_s = base + total;
        __syncthreads();
    }
    if (threadIdx.x == 0) g_rowptr[NN] = base_s;
}
__global__ void cursor_kernel() {
    int i = blockIdx.x * blockDim.x + threadIdx.x;
    if (i < NN) g_cursor[i] = g_rowptr[i];
}
__global__ void fill_kernel() {
    int e = blockIdx.x * blockDim.x + threadIdx.x;
    if (e < NE) {
        int pos = atomicAdd(&g_cursor[g_dst[e]], 1);
        g_ids[pos] = g_src[e];
    }
}

// ---------------- split-precision conversions ----------------
// A [M,K] fp32 -> A' [M,3K] bf16 : [hi | lo | hi]
__global__ void convA_kernel(const float* __restrict__ A, __nv_bfloat16* __restrict__ Ap,
                             int M, int K) {
    int idx = blockIdx.x * blockDim.x + threadIdx.x;
    if (idx >= M * K) return;
    int m = idx / K, k = idx - m * K;
    float a = A[idx];
    __nv_bfloat16 hi = __float2bfloat16(a);
    __nv_bfloat16 lo = __float2bfloat16(a - __bfloat162float(hi));
    size_t base = (size_t)m * 3 * K;
    Ap[base + k] = hi;
    Ap[base + K + k] = lo;
    Ap[base + 2 * K + k] = hi;
}
// W [K,256] fp32 -> W' [256,3K] bf16 K-major transposed : [hi | hi | lo]
__global__ void convW_kernel(const float* __restrict__ W, __nv_bfloat16* __restrict__ Wp, int K) {
    int idx = blockIdx.x * blockDim.x + threadIdx.x;
    if (idx >= K * 256) return;
    int k = idx >> 8, n = idx & 255;
    float a = W[idx];
    __nv_bfloat16 hi = __float2bfloat16(a);
    __nv_bfloat16 lo = __float2bfloat16(a - __bfloat162float(hi));
    size_t base = (size_t)n * 3 * K;
    Wp[base + k] = hi;
    Wp[base + K + k] = hi;
    Wp[base + 2 * K + k] = lo;
}

// ---------------- HMMA GEMM: C[M,256] = A'[M,Kp] x W'[256,Kp]^T ----------------
// CTA tile 128x128 (grid.x = 2 col tiles), 8 warps as 4(m) x 2(n) -> warp tile 32x64.
// BK=32, cp.async double-buffered smem, ldmatrix.x4 operand fetch.
#define BKH 32
#define TSTR 40                     // smem row stride in halves (80B, ldmatrix conflict-free)
#define TILE_HALVES (128 * TSTR)    // 5120 halves = 10240 B per tile

__global__ __launch_bounds__(256) void hgemm_kernel(const __nv_bfloat16* __restrict__ A,
                                                    const __nv_bfloat16* __restrict__ B,
                                                    float* __restrict__ C,
                                                    int M, int Kp) {
    __shared__ __nv_bfloat16 sA[2][TILE_HALVES];
    __shared__ __nv_bfloat16 sB[2][TILE_HALVES];
    const int tid = threadIdx.x;
    const int lane = tid & 31;
    const int wid = tid >> 5;
    const int warp_m = (wid >> 1) * 32;   // 0,32,64,96
    const int warp_n = (wid & 1) * 64;    // 0,64
    const int rowTile = blockIdx.y;
    const int colTile = blockIdx.x;

    const uint32_t saddrA = smem_u32(sA);
    const uint32_t saddrB = smem_u32(sB);

    float acc[2][8][4];
#pragma unroll
    for (int i = 0; i < 2; i++)
#pragma unroll
        for (int j = 0; j < 8; j++)
#pragma unroll
            for (int q = 0; q < 4; q++) acc[i][j][q] = 0.f;

    const int nCh = Kp >> 5;

    // per-thread tile-load coords: 512 float4 per tile, 2 per thread
    const int r0 = tid >> 2;                 // rows 0..63
    const int c0 = (tid & 3) << 3;           // half-cols 0,8,16,24

    // ldmatrix per-lane address offsets (in halves, within a tile buffer)
    // A frag: row = warp_m + mi*16 + (lane&15); col = ks*16 + (lane>>4)*8
    const int aRow = warp_m + (lane & 15);
    const int aCol = (lane >> 4) << 3;
    // B frag: nrow = warp_n + g*16 + (lane&7) + ((lane>>4)&1)*8; col = ks*16 + ((lane>>3)&1)*8
    const int bRow = warp_n + (lane & 7) + (((lane >> 4) & 1) << 3);
    const int bCol = ((lane >> 3) & 1) << 3;

    auto load_tile = [&](int c, int buf) {
#pragma unroll
        for (int it = 0; it < 2; it++) {
            int row = r0 + it * 64;
            int grow = rowTile * 128 + row;
            int gsafe = grow < M ? grow : (M - 1);
            const __nv_bfloat16* srcA = A + (size_t)gsafe * Kp + c * BKH + c0;
            uint32_t dstA = saddrA + (uint32_t)(buf * TILE_HALVES + row * TSTR + c0) * 2;
            cp_async16(dstA, srcA, grow < M ? 16 : 0);
            const __nv_bfloat16* srcB = B + (size_t)(colTile * 128 + row) * Kp + c * BKH + c0;
            uint32_t dstB = saddrB + (uint32_t)(buf * TILE_HALVES + row * TSTR + c0) * 2;
            cp_async16(dstB, srcB, 16);
        }
        CP_COMMIT();
    };

    load_tile(0, 0);

    for (int c = 0; c < nCh; c++) {
        CP_WAIT0();
        __syncthreads();
        if (c + 1 < nCh) load_tile(c + 1, (c + 1) & 1);

        const int buf = c & 1;
        const uint32_t baseA = saddrA + (uint32_t)(buf * TILE_HALVES) * 2;
        const uint32_t baseB = saddrB + (uint32_t)(buf * TILE_HALVES) * 2;
#pragma unroll
        for (int ks = 0; ks < 2; ks++) {
            uint32_t aF[2][4];
#pragma unroll
            for (int mi = 0; mi < 2; mi++) {
                uint32_t addr = baseA + (uint32_t)((aRow + mi * 16) * TSTR + ks * 16 + aCol) * 2;
                asm volatile("ldmatrix.sync.aligned.m8n8.x4.shared.b16 {%0,%1,%2,%3}, [%4];"
                             : "=r"(aF[mi][0]), "=r"(aF[mi][1]), "=r"(aF[mi][2]), "=r"(aF[mi][3])
                             : "r"(addr));
            }
            uint32_t bF[4][4];
#pragma unroll
            for (int g = 0; g < 4; g++) {
                uint32_t addr = baseB + (uint32_t)((bRow + g * 16) * TSTR + ks * 16 + bCol) * 2;
                asm volatile("ldmatrix.sync.aligned.m8n8.x4.shared.b16 {%0,%1,%2,%3}, [%4];"
                             : "=r"(bF[g][0]), "=r"(bF[g][1]), "=r"(bF[g][2]), "=r"(bF[g][3])
                             : "r"(addr));
            }
#pragma unroll
            for (int mi = 0; mi < 2; mi++)
#pragma unroll
                for (int nj = 0; nj < 8; nj++) {
                    uint32_t b0 = bF[nj >> 1][(nj & 1) * 2];
                    uint32_t b1 = bF[nj >> 1][(nj & 1) * 2 + 1];
                    asm volatile(
                        "mma.sync.aligned.m16n8k16.row.col.f32.bf16.bf16.f32 "
                        "{%0,%1,%2,%3}, {%4,%5,%6,%7}, {%8,%9}, {%0,%1,%2,%3};"
                        : "+f"(acc[mi][nj][0]), "+f"(acc[mi][nj][1]),
                          "+f"(acc[mi][nj][2]), "+f"(acc[mi][nj][3])
                        : "r"(aF[mi][0]), "r"(aF[mi][1]), "r"(aF[mi][2]), "r"(aF[mi][3]),
                          "r"(b0), "r"(b1));
                }
        }
    }

    // epilogue
#pragma unroll
    for (int mi = 0; mi < 2; mi++) {
        int gr = rowTile * 128 + warp_m + mi * 16 + (lane >> 2);
        int gcBase = colTile * 128 + warp_n + (lane & 3) * 2;
#pragma unroll
        for (int nj = 0; nj < 8; nj++) {
            int gc = gcBase + nj * 8;
            if (gr < M)
                *(float2*)(C + (size_t)gr * 256 + gc) = make_float2(acc[mi][nj][0], acc[mi][nj][1]);
            if (gr + 8 < M)
                *(float2*)(C + (size_t)(gr + 8) * 256 + gc) = make_float2(acc[mi][nj][2], acc[mi][nj][3]);
        }
    }
}

// ---------------- per-node attention logits ----------------
__global__ void alphas_kernel(const float* __restrict__ h,
                              const float* __restrict__ avs,
                              const float* __restrict__ avd) {
    int node = blockIdx.x * (blockDim.x >> 5) + (threadIdx.x >> 5);
    int lane = threadIdx.x & 31;
    if (node >= NN) return;
    const float4* hr = (const float4*)(h + (size_t)node * HIDF);
    const float4* s4 = (const float4*)avs;
    const float4* d4 = (const float4*)avd;
    float ss = 0.f, sd = 0.f;
#pragma unroll
    for (int k = 0; k < 2; k++) {
        int c = lane + k * 32;
        float4 hv = hr[c];
        float4 a = s4[c];
        float4 b = d4[c];
        ss += hv.x * a.x + hv.y * a.y + hv.z * a.z + hv.w * a.w;
        sd += hv.x * b.x + hv.y * b.y + hv.z * b.z + hv.w * b.w;
    }
#pragma unroll
    for (int o = 16; o; o >>= 1) {
        ss += __shfl_xor_sync(0xffffffffu, ss, o);
        sd += __shfl_xor_sync(0xffffffffu, sd, o);
    }
    if (lane == 0) {
        g_as[node] = ss;
        g_ad[node] = sd;
    }
}

// ---------------- warp-per-node segment softmax + weighted aggregation ----------------
__global__ void aggregate_kernel(const float* __restrict__ h,
                                 const float* __restrict__ bias,
                                 float* __restrict__ out,
                                 int do_relu) {
    int node = blockIdx.x * (blockDim.x >> 5) + (threadIdx.x >> 5);
    int lane = threadIdx.x & 31;
    if (node >= NN) return;
    int beg = g_rowptr[node];
    int end = g_rowptr[node + 1];
    float add = g_ad[node];
    float e_self = lrelu(g_as[node] + add);

    float m = e_self;
    for (int j = beg + lane; j < end; j += 32) {
        int sj = g_ids[j];
        m = fmaxf(m, lrelu(g_as[sj] + add));
    }
#pragma unroll
    for (int o = 16; o; o >>= 1) m = fmaxf(m, __shfl_xor_sync(0xffffffffu, m, o));

    float s = 0.f;
    for (int j = beg + lane; j < end; j += 32) {
        int sj = g_ids[j];
        s += __expf(lrelu(g_as[sj] + add) - m);
    }
#pragma unroll
    for (int o = 16; o; o >>= 1) s += __shfl_xor_sync(0xffffffffu, s, o);
    s += __expf(e_self - m);
    float inv = 1.0f / s;

    int c0 = lane;
    int c1 = lane + 32;
    float w = __expf(e_self - m) * inv;
    const float4* hp = (const float4*)(h + (size_t)node * HIDF);
    float4 v0 = hp[c0], v1 = hp[c1];
    float4 acc0 = make_float4(w * v0.x, w * v0.y, w * v0.z, w * v0.w);
    float4 acc1 = make_float4(w * v1.x, w * v1.y, w * v1.z, w * v1.w);
    for (int j = beg; j < end; j++) {
        int sj = g_ids[j];
        float wj = __expf(lrelu(g_as[sj] + add) - m) * inv;
        const float4* hq = (const float4*)(h + (size_t)sj * HIDF);
        float4 u0 = hq[c0], u1 = hq[c1];
        acc0.x += wj * u0.x; acc0.y += wj * u0.y; acc0.z += wj * u0.z; acc0.w += wj * u0.w;
        acc1.x += wj * u1.x; acc1.y += wj * u1.y; acc1.z += wj * u1.z; acc1.w += wj * u1.w;
    }
    const float4* b4 = (const float4*)bias;
    float4 b0 = b4[c0], b1 = b4[c1];
    acc0.x += b0.x; acc0.y += b0.y; acc0.z += b0.z; acc0.w += b0.w;
    acc1.x += b1.x; acc1.y += b1.y; acc1.z += b1.z; acc1.w += b1.w;
    if (do_relu) {
        acc0.x = fmaxf(acc0.x, 0.f); acc0.y = fmaxf(acc0.y, 0.f);
        acc0.z = fmaxf(acc0.z, 0.f); acc0.w = fmaxf(acc0.w, 0.f);
        acc1.x = fmaxf(acc1.x, 0.f); acc1.y = fmaxf(acc1.y, 0.f);
        acc1.z = fmaxf(acc1.z, 0.f); acc1.w = fmaxf(acc1.w, 0.f);
    }
    float4* op = (float4*)(out + (size_t)node * HIDF);
    op[c0] = acc0;
    op[c1] = acc1;
}

// ---------------- edge head: out[e] = P1[src[e]] + P2[dst[e]] + lin_b ----------------
__global__ void edge_out_kernel(const float* __restrict__ P1,
                                const float* __restrict__ P2,
                                const float* __restrict__ lin_b,
                                float* __restrict__ out) {
    int e = blockIdx.x * (blockDim.x >> 5) + (threadIdx.x >> 5);
    int lane = threadIdx.x & 31;
    if (e >= NE) return;
    int s = g_src[e];
    int d = g_dst[e];
    const float4* p1 = (const float4*)(P1 + (size_t)s * HIDF);
    const float4* p2 = (const float4*)(P2 + (size_t)d * HIDF);
    const float4* b4 = (const float4*)lin_b;
    float4* o4 = (float4*)(out + (size_t)e * HIDF);
#pragma unroll
    for (int k = 0; k < 2; k++) {
        int c = lane + k * 32;
        float4 a = p1[c];
        float4 b = p2[c];
        float4 bb = b4[c];
        o4[c] = make_float4(a.x + b.x + bb.x, a.y + b.y + bb.y,
                            a.z + b.z + bb.z, a.w + b.w + bb.w);
    }
}

// ---------------- host ----------------
extern "C" void kernel_launch(void* const* d_in, const int* in_sizes, int n_in,
                              void* d_out, int out_size) {
    const float* x      = (const float*)d_in[0];
    const void*  eidx   = d_in[1];
    const float* W1     = (const float*)d_in[2];
    const float* a1_src = (const float*)d_in[3];
    const float* a1_dst = (const float*)d_in[4];
    const float* b1     = (const float*)d_in[5];
    const float* W2     = (const float*)d_in[6];
    const float* a2_src = (const float*)d_in[7];
    const float* a2_dst = (const float*)d_in[8];
    const float* b2     = (const float*)d_in[9];
    const float* lin_W  = (const float*)d_in[10];
    const float* lin_b  = (const float*)d_in[11];
    float* out = (float*)d_out;

    float *bufA, *bufB, *bufC;
    __nv_bfloat16 *abf, *wbf, *wbf2;
    cudaGetSymbolAddress((void**)&bufA, g_bufA);
    cudaGetSymbolAddress((void**)&bufB, g_bufB);
    cudaGetSymbolAddress((void**)&bufC, g_bufC);
    cudaGetSymbolAddress((void**)&abf, g_abf);
    cudaGetSymbolAddress((void**)&wbf, g_wbf);
    cudaGetSymbolAddress((void**)&wbf2, g_wbf2);

    const int TPB = 256;
    const int edgeBlocks = (NE + TPB - 1) / TPB;
    const int nodeBlocks = (NN + TPB - 1) / TPB;
    const int warpNodeBlocks = (NN + 7) / 8;
    const int warpEdgeBlocks = (NE + 7) / 8;
    dim3 ggrid(2, (NN + 127) / 128);

    // --- normalize edge index + CSR build ---
    detect_kernel<<<1, 256>>>((const int*)eidx);
    convert_kernel<<<edgeBlocks, TPB>>>(eidx);
    zero_cnt_kernel<<<nodeBlocks, TPB>>>();
    count_kernel<<<edgeBlocks, TPB>>>();
    scan_kernel<<<1, 1024>>>();
    cursor_kernel<<<nodeBlocks, TPB>>>();
    fill_kernel<<<edgeBlocks, TPB>>>();

    // --- layer 1: h1 = x @ W1  (K=128 -> K'=384) ---
    convA_kernel<<<(NN * 128 + TPB - 1) / TPB, TPB>>>(x, abf, NN, 128);
    convW_kernel<<<(128 * 256 + TPB - 1) / TPB, TPB>>>(W1, wbf, 128);
    hgemm_kernel<<<ggrid, 256>>>(abf, wbf, bufA, NN, 384);
    alphas_kernel<<<warpNodeBlocks, TPB>>>(bufA, a1_src, a1_dst);
    aggregate_kernel<<<warpNodeBlocks, TPB>>>(bufA, b1, bufB, 1);

    // --- layer 2: h2 = relu_h1 @ W2  (K=256 -> K'=768) ---
    convA_kernel<<<(NN * 256 + TPB - 1) / TPB, TPB>>>(bufB, abf, NN, 256);
    convW_kernel<<<(256 * 256 + TPB - 1) / TPB, TPB>>>(W2, wbf, 256);
    hgemm_kernel<<<ggrid, 256>>>(abf, wbf, bufC, NN, 768);
    alphas_kernel<<<warpNodeBlocks, TPB>>>(bufC, a2_src, a2_dst);
    aggregate_kernel<<<warpNodeBlocks, TPB>>>(bufC, b2, bufA, 0);

    // --- edge head: P1 = h @ lin_W_top, P2 = h @ lin_W_bot ---
    convA_kernel<<<(NN * 256 + TPB - 1) / TPB, TPB>>>(bufA, abf, NN, 256);
    convW_kernel<<<(256 * 256 + TPB - 1) / TPB, TPB>>>(lin_W, wbf, 256);
    convW_kernel<<<(256 * 256 + TPB - 1) / TPB, TPB>>>(lin_W + 256 * 256, wbf2, 256);
    hgemm_kernel<<<ggrid, 256>>>(abf, wbf, bufB, NN, 768);
    hgemm_kernel<<<ggrid, 256>>>(abf, wbf2, bufC, NN, 768);
    edge_out_kernel<<<warpEdgeBlocks, TPB>>>(bufB, bufC, lin_b, out);
}

// round 11
// speedup vs baseline: 1.5288x; 1.5288x over previous
#include <cuda_runtime.h>
#include <cuda_bf16.h>
#include <cstdint>
#include <math.h>

#define NN 50000
#define NE 500000
#define HIDF 256
#define NEG_SLOPE 0.2f

// ---------------- scratch (no allocation allowed) ----------------
__device__ __align__(256) float g_bufA[(size_t)NN * HIDF];
__device__ __align__(256) float g_bufB[(size_t)NN * HIDF];
__device__ __align__(256) float g_bufC[(size_t)NN * HIDF];
__device__ __align__(256) __nv_bfloat16 g_abf[(size_t)NN * 768];   // A' split bf16 (max K'=768)
__device__ __align__(256) __nv_bfloat16 g_wbf[(size_t)256 * 768];  // W' split bf16
__device__ __align__(256) __nv_bfloat16 g_wbf2[(size_t)256 * 768];
__device__ int g_src[NE];
__device__ int g_dst[NE];
__device__ int g_cnt[NN];
__device__ int g_rowptr[NN + 1];
__device__ int g_cursor[NN];
__device__ int g_ids[NE];   // SRC node id of CSR-sorted edge
__device__ float g_as[NN];
__device__ float g_ad[NN];
__device__ int g_is64;

// ---------------- helpers ----------------
__device__ __forceinline__ uint32_t smem_u32(const void* p) {
    uint32_t a;
    asm("{ .reg .u64 t; cvta.to.shared.u64 t, %1; cvt.u32.u64 %0, t; }" : "=r"(a) : "l"(p));
    return a;
}
__device__ __forceinline__ void cp_async16(uint32_t dst, const void* src, int sz) {
    asm volatile("cp.async.cg.shared.global [%0], [%1], 16, %2;" :: "r"(dst), "l"(src), "r"(sz) : "memory");
}
#define CP_COMMIT() asm volatile("cp.async.commit_group;" ::: "memory")
#define CP_WAIT0()  asm volatile("cp.async.wait_group 0;" ::: "memory")

__device__ __forceinline__ float lrelu(float e) { return e > 0.f ? e : NEG_SLOPE * e; }

// ---------------- edge index dtype detection + normalize ----------------
__global__ void detect_kernel(const int* __restrict__ w) {
    __shared__ int sh[256];
    int nz = 0;
    for (int i = 1 + 2 * (int)threadIdx.x; i < 1000000; i += 2 * (int)blockDim.x)
        nz += (w[i] != 0);
    sh[threadIdx.x] = nz;
    __syncthreads();
    for (int off = 128; off; off >>= 1) {
        if ((int)threadIdx.x < off) sh[threadIdx.x] += sh[threadIdx.x + off];
        __syncthreads();
    }
    if (threadIdx.x == 0) g_is64 = (sh[0] == 0) ? 1 : 0;
}

__global__ void convert_kernel(const void* __restrict__ ei) {
    int e = blockIdx.x * blockDim.x + threadIdx.x;
    if (e >= NE) return;
    if (g_is64) {
        const long long* p = (const long long*)ei;
        g_src[e] = (int)p[e];
        g_dst[e] = (int)p[NE + e];
    } else {
        const int* p = (const int*)ei;
        g_src[e] = p[e];
        g_dst[e] = p[NE + e];
    }
}

// ---------------- CSR build (sorted by dst, payload = src id) ----------------
__global__ void zero_cnt_kernel() {
    int i = blockIdx.x * blockDim.x + threadIdx.x;
    if (i < NN) g_cnt[i] = 0;
}
__global__ void count_kernel() {
    int e = blockIdx.x * blockDim.x + threadIdx.x;
    if (e < NE) atomicAdd(&g_cnt[g_dst[e]], 1);
}
__global__ void scan_kernel() {
    __shared__ int sdata[1024];
    __shared__ int base_s;
    if (threadIdx.x == 0) base_s = 0;
    __syncthreads();
    for (int start = 0; start < NN; start += 1024) {
        int i = start + (int)threadIdx.x;
        int v = (i < NN) ? g_cnt[i] : 0;
        sdata[threadIdx.x] = v;
        __syncthreads();
        for (int off = 1; off < 1024; off <<= 1) {
            int t = ((int)threadIdx.x >= off) ? sdata[threadIdx.x - off] : 0;
            __syncthreads();
            sdata[threadIdx.x] += t;
            __syncthreads();
        }
        int incl = sdata[threadIdx.x];
        int total = sdata[1023];
        int base = base_s;
        if (i < NN) g_rowptr[i] = base + incl - v;
        __syncthreads();
        if (threadIdx.x == 0) base_s = base + total;
        __syncthreads();
    }
    if (threadIdx.x == 0) g_rowptr[NN] = base_s;
}
__global__ void cursor_kernel() {
    int i = blockIdx.x * blockDim.x + threadIdx.x;
    if (i < NN) g_cursor[i] = g_rowptr[i];
}
__global__ void fill_kernel() {
    int e = blockIdx.x * blockDim.x + threadIdx.x;
    if (e < NE) {
        int pos = atomicAdd(&g_cursor[g_dst[e]], 1);
        g_ids[pos] = g_src[e];
    }
}

// ---------------- split-precision conversions ----------------
// A [M,K] fp32 -> A' [M,3K] bf16 : [hi | lo | hi]   (only needed for x)
__global__ void convA_kernel(const float* __restrict__ A, __nv_bfloat16* __restrict__ Ap,
                             int M, int K) {
    int idx = blockIdx.x * blockDim.x + threadIdx.x;
    if (idx >= M * K) return;
    int m = idx / K, k = idx - m * K;
    float a = A[idx];
    __nv_bfloat16 hi = __float2bfloat16(a);
    __nv_bfloat16 lo = __float2bfloat16(a - __bfloat162float(hi));
    size_t base = (size_t)m * 3 * K;
    Ap[base + k] = hi;
    Ap[base + K + k] = lo;
    Ap[base + 2 * K + k] = hi;
}
// W [K,256] fp32 -> W' [256,3K] bf16 K-major transposed : [hi | hi | lo]
__global__ void convW_kernel(const float* __restrict__ W, __nv_bfloat16* __restrict__ Wp, int K) {
    int idx = blockIdx.x * blockDim.x + threadIdx.x;
    if (idx >= K * 256) return;
    int k = idx >> 8, n = idx & 255;
    float a = W[idx];
    __nv_bfloat16 hi = __float2bfloat16(a);
    __nv_bfloat16 lo = __float2bfloat16(a - __bfloat162float(hi));
    size_t base = (size_t)n * 3 * K;
    Wp[base + k] = hi;
    Wp[base + K + k] = hi;
    Wp[base + 2 * K + k] = lo;
}

// ---------------- HMMA GEMM: C[M,256] = A'[M,Kp] x W'[256,Kp]^T ----------------
// CTA tile 128(M) x 256(N), 8 warps as 2(m) x 4(n) -> warp tile 64x64.
// BK = 64 halves, cp.async double-buffered dynamic smem, ldmatrix.x4.
#define BKH 64
#define TSTR 72                         // smem row stride in halves (144B, LDSM conflict-free)
#define A_HALVES (128 * TSTR)           // 9216 halves / buffer
#define B_HALVES (256 * TSTR)           // 18432 halves / buffer
#define SMEM_HALVES (2 * A_HALVES + 2 * B_HALVES)  // 55296 halves = 110592 B

__global__ __launch_bounds__(256) void hgemm_kernel(const __nv_bfloat16* __restrict__ A,
                                                    const __nv_bfloat16* __restrict__ B,
                                                    float* __restrict__ C,
                                                    int M, int Kp) {
    extern __shared__ __nv_bfloat16 smh[];
    const int tid = threadIdx.x;
    const int lane = tid & 31;
    const int wid = tid >> 5;
    const int warp_m = (wid >> 2) * 64;   // 0,64
    const int warp_n = (wid & 3) * 64;    // 0,64,128,192
    const int rowTile = blockIdx.x;

    const uint32_t sbase = smem_u32(smh);

    float acc[4][8][4];
#pragma unroll
    for (int i = 0; i < 4; i++)
#pragma unroll
        for (int j = 0; j < 8; j++)
#pragma unroll
            for (int q = 0; q < 4; q++) acc[i][j][q] = 0.f;

    const int nCh = Kp >> 6;

    // ldmatrix per-lane coords
    const int aRow = warp_m + (lane & 15);
    const int aCol = (lane >> 4) << 3;
    const int bRow = warp_n + (lane & 7) + (((lane >> 4) & 1) << 3);
    const int bCol = ((lane >> 3) & 1) << 3;

    auto load_tile = [&](int c, int buf) {
        // A: 128 rows x 64 halves = 1024 x 16B, 4 per thread
#pragma unroll
        for (int i = 0; i < 4; i++) {
            int linear = i * 256 + tid;
            int row = linear >> 3;
            int c8 = (linear & 7) << 3;
            int grow = rowTile * 128 + row;
            int gsafe = grow < M ? grow : (M - 1);
            const __nv_bfloat16* src = A + (size_t)gsafe * Kp + c * BKH + c8;
            uint32_t dst = sbase + (uint32_t)(buf * A_HALVES + row * TSTR + c8) * 2;
            cp_async16(dst, src, grow < M ? 16 : 0);
        }
        // B: 256 rows x 64 halves = 2048 x 16B, 8 per thread
#pragma unroll
        for (int i = 0; i < 8; i++) {
            int linear = i * 256 + tid;
            int row = linear >> 3;
            int c8 = (linear & 7) << 3;
            const __nv_bfloat16* src = B + (size_t)row * Kp + c * BKH + c8;
            uint32_t dst = sbase + (uint32_t)(2 * A_HALVES + buf * B_HALVES + row * TSTR + c8) * 2;
            cp_async16(dst, src, 16);
        }
        CP_COMMIT();
    };

    load_tile(0, 0);

    for (int c = 0; c < nCh; c++) {
        CP_WAIT0();
        __syncthreads();
        if (c + 1 < nCh) load_tile(c + 1, (c + 1) & 1);

        const int buf = c & 1;
        const uint32_t baseA = sbase + (uint32_t)(buf * A_HALVES) * 2;
        const uint32_t baseB = sbase + (uint32_t)(2 * A_HALVES + buf * B_HALVES) * 2;
#pragma unroll
        for (int ks = 0; ks < 4; ks++) {
            uint32_t aF[4][4];
#pragma unroll
            for (int mi = 0; mi < 4; mi++) {
                uint32_t addr = baseA + (uint32_t)((aRow + mi * 16) * TSTR + ks * 16 + aCol) * 2;
                asm volatile("ldmatrix.sync.aligned.m8n8.x4.shared.b16 {%0,%1,%2,%3}, [%4];"
                             : "=r"(aF[mi][0]), "=r"(aF[mi][1]), "=r"(aF[mi][2]), "=r"(aF[mi][3])
                             : "r"(addr));
            }
            uint32_t bF[4][4];
#pragma unroll
            for (int g = 0; g < 4; g++) {
                uint32_t addr = baseB + (uint32_t)((bRow + g * 16) * TSTR + ks * 16 + bCol) * 2;
                asm volatile("ldmatrix.sync.aligned.m8n8.x4.shared.b16 {%0,%1,%2,%3}, [%4];"
                             : "=r"(bF[g][0]), "=r"(bF[g][1]), "=r"(bF[g][2]), "=r"(bF[g][3])
                             : "r"(addr));
            }
#pragma unroll
            for (int mi = 0; mi < 4; mi++)
#pragma unroll
                for (int nj = 0; nj < 8; nj++) {
                    uint32_t b0 = bF[nj >> 1][(nj & 1) * 2];
                    uint32_t b1 = bF[nj >> 1][(nj & 1) * 2 + 1];
                    asm volatile(
                        "mma.sync.aligned.m16n8k16.row.col.f32.bf16.bf16.f32 "
                        "{%0,%1,%2,%3}, {%4,%5,%6,%7}, {%8,%9}, {%0,%1,%2,%3};"
                        : "+f"(acc[mi][nj][0]), "+f"(acc[mi][nj][1]),
                          "+f"(acc[mi][nj][2]), "+f"(acc[mi][nj][3])
                        : "r"(aF[mi][0]), "r"(aF[mi][1]), "r"(aF[mi][2]), "r"(aF[mi][3]),
                          "r"(b0), "r"(b1));
                }
        }
    }

    // epilogue
#pragma unroll
    for (int mi = 0; mi < 4; mi++) {
        int gr = rowTile * 128 + warp_m + mi * 16 + (lane >> 2);
        int gcBase = warp_n + (lane & 3) * 2;
#pragma unroll
        for (int nj = 0; nj < 8; nj++) {
            int gc = gcBase + nj * 8;
            if (gr < M)
                *(float2*)(C + (size_t)gr * 256 + gc) = make_float2(acc[mi][nj][0], acc[mi][nj][1]);
            if (gr + 8 < M)
                *(float2*)(C + (size_t)(gr + 8) * 256 + gc) = make_float2(acc[mi][nj][2], acc[mi][nj][3]);
        }
    }
}

// ---------------- per-node attention logits ----------------
__global__ void alphas_kernel(const float* __restrict__ h,
                              const float* __restrict__ avs,
                              const float* __restrict__ avd) {
    int node = blockIdx.x * (blockDim.x >> 5) + (threadIdx.x >> 5);
    int lane = threadIdx.x & 31;
    if (node >= NN) return;
    const float4* hr = (const float4*)(h + (size_t)node * HIDF);
    const float4* s4 = (const float4*)avs;
    const float4* d4 = (const float4*)avd;
    float ss = 0.f, sd = 0.f;
#pragma unroll
    for (int k = 0; k < 2; k++) {
        int c = lane + k * 32;
        float4 hv = hr[c];
        float4 a = s4[c];
        float4 b = d4[c];
        ss += hv.x * a.x + hv.y * a.y + hv.z * a.z + hv.w * a.w;
        sd += hv.x * b.x + hv.y * b.y + hv.z * b.z + hv.w * b.w;
    }
#pragma unroll
    for (int o = 16; o; o >>= 1) {
        ss += __shfl_xor_sync(0xffffffffu, ss, o);
        sd += __shfl_xor_sync(0xffffffffu, sd, o);
    }
    if (lane == 0) {
        g_as[node] = ss;
        g_ad[node] = sd;
    }
}

// ---------------- split-bf16 float4 store helper ----------------
__device__ __forceinline__ void store_split4(__nv_bfloat16* p_hi, __nv_bfloat16* p_lo,
                                             __nv_bfloat16* p_hi2, float4 v) {
    __nv_bfloat16 h0 = __float2bfloat16(v.x), h1 = __float2bfloat16(v.y);
    __nv_bfloat16 h2 = __float2bfloat16(v.z), h3 = __float2bfloat16(v.w);
    __nv_bfloat16 l0 = __float2bfloat16(v.x - __bfloat162float(h0));
    __nv_bfloat16 l1 = __float2bfloat16(v.y - __bfloat162float(h1));
    __nv_bfloat16 l2 = __float2bfloat16(v.z - __bfloat162float(h2));
    __nv_bfloat16 l3 = __float2bfloat16(v.w - __bfloat162float(h3));
    ushort4 hs = make_ushort4(__bfloat16_as_ushort(h0), __bfloat16_as_ushort(h1),
                              __bfloat16_as_ushort(h2), __bfloat16_as_ushort(h3));
    ushort4 ls = make_ushort4(__bfloat16_as_ushort(l0), __bfloat16_as_ushort(l1),
                              __bfloat16_as_ushort(l2), __bfloat16_as_ushort(l3));
    *(ushort4*)p_hi = hs;
    *(ushort4*)p_lo = ls;
    *(ushort4*)p_hi2 = hs;
}

// ---------------- warp-per-node segment softmax + aggregation (split-bf16 output) ----------
__global__ void aggregate_kernel(const float* __restrict__ h,
                                 const float* __restrict__ bias,
                                 __nv_bfloat16* __restrict__ Ap,
                                 int do_relu) {
    int node = blockIdx.x * (blockDim.x >> 5) + (threadIdx.x >> 5);
    int lane = threadIdx.x & 31;
    if (node >= NN) return;
    int beg = g_rowptr[node];
    int end = g_rowptr[node + 1];
    float add = g_ad[node];
    float e_self = lrelu(g_as[node] + add);

    float m = e_self;
    for (int j = beg + lane; j < end; j += 32) {
        int sj = g_ids[j];
        m = fmaxf(m, lrelu(g_as[sj] + add));
    }
#pragma unroll
    for (int o = 16; o; o >>= 1) m = fmaxf(m, __shfl_xor_sync(0xffffffffu, m, o));

    float s = 0.f;
    for (int j = beg + lane; j < end; j += 32) {
        int sj = g_ids[j];
        s += __expf(lrelu(g_as[sj] + add) - m);
    }
#pragma unroll
    for (int o = 16; o; o >>= 1) s += __shfl_xor_sync(0xffffffffu, s, o);
    s += __expf(e_self - m);
    float inv = 1.0f / s;

    int c0 = lane;
    int c1 = lane + 32;
    float w = __expf(e_self - m) * inv;
    const float4* hp = (const float4*)(h + (size_t)node * HIDF);
    float4 v0 = hp[c0], v1 = hp[c1];
    float4 acc0 = make_float4(w * v0.x, w * v0.y, w * v0.z, w * v0.w);
    float4 acc1 = make_float4(w * v1.x, w * v1.y, w * v1.z, w * v1.w);
    for (int j = beg; j < end; j++) {
        int sj = g_ids[j];
        float wj = __expf(lrelu(g_as[sj] + add) - m) * inv;
        const float4* hq = (const float4*)(h + (size_t)sj * HIDF);
        float4 u0 = hq[c0], u1 = hq[c1];
        acc0.x += wj * u0.x; acc0.y += wj * u0.y; acc0.z += wj * u0.z; acc0.w += wj * u0.w;
        acc1.x += wj * u1.x; acc1.y += wj * u1.y; acc1.z += wj * u1.z; acc1.w += wj * u1.w;
    }
    const float4* b4 = (const float4*)bias;
    float4 b0 = b4[c0], b1 = b4[c1];
    acc0.x += b0.x; acc0.y += b0.y; acc0.z += b0.z; acc0.w += b0.w;
    acc1.x += b1.x; acc1.y += b1.y; acc1.z += b1.z; acc1.w += b1.w;
    if (do_relu) {
        acc0.x = fmaxf(acc0.x, 0.f); acc0.y = fmaxf(acc0.y, 0.f);
        acc0.z = fmaxf(acc0.z, 0.f); acc0.w = fmaxf(acc0.w, 0.f);
        acc1.x = fmaxf(acc1.x, 0.f); acc1.y = fmaxf(acc1.y, 0.f);
        acc1.z = fmaxf(acc1.z, 0.f); acc1.w = fmaxf(acc1.w, 0.f);
    }
    // write split-bf16 [hi | lo | hi] rows of width 768
    __nv_bfloat16* row = Ap + (size_t)node * 768;
    store_split4(row + 4 * lane, row + 256 + 4 * lane, row + 512 + 4 * lane, acc0);
    store_split4(row + 128 + 4 * lane, row + 384 + 4 * lane, row + 640 + 4 * lane, acc1);
}

// ---------------- edge head: out[e] = P1[src[e]] + P2[dst[e]] + lin_b ----------------
__global__ void edge_out_kernel(const float* __restrict__ P1,
                                const float* __restrict__ P2,
                                const float* __restrict__ lin_b,
                                float* __restrict__ out) {
    int e = blockIdx.x * (blockDim.x >> 5) + (threadIdx.x >> 5);
    int lane = threadIdx.x & 31;
    if (e >= NE) return;
    int s = g_src[e];
    int d = g_dst[e];
    const float4* p1 = (const float4*)(P1 + (size_t)s * HIDF);
    const float4* p2 = (const float4*)(P2 + (size_t)d * HIDF);
    const float4* b4 = (const float4*)lin_b;
    float4* o4 = (float4*)(out + (size_t)e * HIDF);
#pragma unroll
    for (int k = 0; k < 2; k++) {
        int c = lane + k * 32;
        float4 a = p1[c];
        float4 b = p2[c];
        float4 bb = b4[c];
        float4 r = make_float4(a.x + b.x + bb.x, a.y + b.y + bb.y,
                               a.z + b.z + bb.z, a.w + b.w + bb.w);
        // streaming store: output is write-once, keep L2 for the gather tables
        asm volatile("st.global.cs.v4.f32 [%0], {%1,%2,%3,%4};"
                     :: "l"(o4 + c), "f"(r.x), "f"(r.y), "f"(r.z), "f"(r.w) : "memory");
    }
}

// ---------------- host ----------------
extern "C" void kernel_launch(void* const* d_in, const int* in_sizes, int n_in,
                              void* d_out, int out_size) {
    const float* x      = (const float*)d_in[0];
    const void*  eidx   = d_in[1];
    const float* W1     = (const float*)d_in[2];
    const float* a1_src = (const float*)d_in[3];
    const float* a1_dst = (const float*)d_in[4];
    const float* b1     = (const float*)d_in[5];
    const float* W2     = (const float*)d_in[6];
    const float* a2_src = (const float*)d_in[7];
    const float* a2_dst = (const float*)d_in[8];
    const float* b2     = (const float*)d_in[9];
    const float* lin_W  = (const float*)d_in[10];
    const float* lin_b  = (const float*)d_in[11];
    float* out = (float*)d_out;

    float *bufA, *bufB, *bufC;
    __nv_bfloat16 *abf, *wbf, *wbf2;
    cudaGetSymbolAddress((void**)&bufA, g_bufA);
    cudaGetSymbolAddress((void**)&bufB, g_bufB);
    cudaGetSymbolAddress((void**)&bufC, g_bufC);
    cudaGetSymbolAddress((void**)&abf, g_abf);
    cudaGetSymbolAddress((void**)&wbf, g_wbf);
    cudaGetSymbolAddress((void**)&wbf2, g_wbf2);

    const int SMEM_BYTES = SMEM_HALVES * 2;
    cudaFuncSetAttribute(hgemm_kernel, cudaFuncAttributeMaxDynamicSharedMemorySize, SMEM_BYTES);

    const int TPB = 256;
    const int edgeBlocks = (NE + TPB - 1) / TPB;
    const int nodeBlocks = (NN + TPB - 1) / TPB;
    const int warpNodeBlocks = (NN + 7) / 8;
    const int warpEdgeBlocks = (NE + 7) / 8;
    const int gemmBlocks = (NN + 127) / 128;

    // ordered so launch #6 (profiled) is the first hgemm
    convA_kernel<<<(NN * 128 + TPB - 1) / TPB, TPB>>>(x, abf, NN, 128);        // 1
    convW_kernel<<<(128 * 256 + TPB - 1) / TPB, TPB>>>(W1, wbf, 128);          // 2
    detect_kernel<<<1, 256>>>((const int*)eidx);                               // 3
    convert_kernel<<<edgeBlocks, TPB>>>(eidx);                                 // 4
    zero_cnt_kernel<<<nodeBlocks, TPB>>>();                                    // 5
    hgemm_kernel<<<gemmBlocks, 256, SMEM_BYTES>>>(abf, wbf, bufA, NN, 384);    // 6  <- ncu
    count_kernel<<<edgeBlocks, TPB>>>();                                       // 7
    scan_kernel<<<1, 1024>>>();                                                // 8
    cursor_kernel<<<nodeBlocks, TPB>>>();                                      // 9
    fill_kernel<<<edgeBlocks, TPB>>>();                                        // 10
    alphas_kernel<<<warpNodeBlocks, TPB>>>(bufA, a1_src, a1_dst);              // 11
    aggregate_kernel<<<warpNodeBlocks, TPB>>>(bufA, b1, abf, 1);               // 12

    convW_kernel<<<(256 * 256 + TPB - 1) / TPB, TPB>>>(W2, wbf, 256);          // 13
    hgemm_kernel<<<gemmBlocks, 256, SMEM_BYTES>>>(abf, wbf, bufB, NN, 768);    // 14
    alphas_kernel<<<warpNodeBlocks, TPB>>>(bufB, a2_src, a2_dst);              // 15
    aggregate_kernel<<<warpNodeBlocks, TPB>>>(bufB, b2, abf, 0);               // 16

    convW_kernel<<<(256 * 256 + TPB - 1) / TPB, TPB>>>(lin_W, wbf, 256);       // 17
    convW_kernel<<<(256 * 256 + TPB - 1) / TPB, TPB>>>(lin_W + 256 * 256, wbf2, 256); // 18
    hgemm_kernel<<<gemmBlocks, 256, SMEM_BYTES>>>(abf, wbf, bufA, NN, 768);    // 19
    hgemm_kernel<<<gemmBlocks, 256, SMEM_BYTES>>>(abf, wbf2, bufC, NN, 768);   // 20
    edge_out_kernel<<<warpEdgeBlocks, TPB>>>(bufA, bufC, lin_b, out);          // 21
}

// round 13
// speedup vs baseline: 1.5372x; 1.0055x over previous
#include <cuda_runtime.h>
#include <cuda_bf16.h>
#include <cstdint>
#include <math.h>

#define NN 50000
#define NE 500000
#define HIDF 256
#define NEG_SLOPE 0.2f

// ---------------- scratch (no allocation allowed) ----------------
__device__ __align__(256) float g_bufA[(size_t)NN * HIDF];
__device__ __align__(256) float g_bufB[(size_t)NN * HIDF];
__device__ __align__(256) __nv_bfloat16 g_abf[(size_t)NN * 768];   // A' split bf16 (max K'=768)
__device__ __align__(256) __nv_bfloat16 g_wbf[(size_t)512 * 768];  // W' split bf16 (head: 512 rows)
__device__ int g_src[NE];
__device__ int g_dst[NE];
__device__ int g_cnt[NN];
__device__ int g_rowptr[NN + 1];
__device__ int g_cursor[NN];
__device__ int g_ids[NE];   // SRC node id of CSR-sorted edge
__device__ float g_as[NN];
__device__ float g_ad[NN];
__device__ int g_is64;

// ---------------- helpers ----------------
__device__ __forceinline__ uint32_t smem_u32(const void* p) {
    uint32_t a;
    asm("{ .reg .u64 t; cvta.to.shared.u64 t, %1; cvt.u32.u64 %0, t; }" : "=r"(a) : "l"(p));
    return a;
}
__device__ __forceinline__ void cp_async16(uint32_t dst, const void* src, int sz) {
    asm volatile("cp.async.cg.shared.global [%0], [%1], 16, %2;" :: "r"(dst), "l"(src), "r"(sz) : "memory");
}
#define CP_COMMIT() asm volatile("cp.async.commit_group;" ::: "memory")
#define CP_WAIT0()  asm volatile("cp.async.wait_group 0;" ::: "memory")

__device__ __forceinline__ float lrelu(float e) { return e > 0.f ? e : NEG_SLOPE * e; }

// ---------------- edge index dtype detection + normalize ----------------
__global__ void detect_kernel(const int* __restrict__ w) {
    __shared__ int sh[256];
    int nz = 0;
    for (int i = 1 + 2 * (int)threadIdx.x; i < 1000000; i += 2 * (int)blockDim.x)
        nz += (w[i] != 0);
    sh[threadIdx.x] = nz;
    __syncthreads();
    for (int off = 128; off; off >>= 1) {
        if ((int)threadIdx.x < off) sh[threadIdx.x] += sh[threadIdx.x + off];
        __syncthreads();
    }
    if (threadIdx.x == 0) g_is64 = (sh[0] == 0) ? 1 : 0;
}

__global__ void convert_kernel(const void* __restrict__ ei) {
    int e = blockIdx.x * blockDim.x + threadIdx.x;
    if (e >= NE) return;
    if (g_is64) {
        const long long* p = (const long long*)ei;
        g_src[e] = (int)p[e];
        g_dst[e] = (int)p[NE + e];
    } else {
        const int* p = (const int*)ei;
        g_src[e] = p[e];
        g_dst[e] = p[NE + e];
    }
}

// ---------------- CSR build (sorted by dst, payload = src id) ----------------
__global__ void zero_cnt_kernel() {
    int i = blockIdx.x * blockDim.x + threadIdx.x;
    if (i < NN) g_cnt[i] = 0;
}
__global__ void count_kernel() {
    int e = blockIdx.x * blockDim.x + threadIdx.x;
    if (e < NE) atomicAdd(&g_cnt[g_dst[e]], 1);
}
__global__ void scan_kernel() {
    __shared__ int sdata[1024];
    __shared__ int base_s;
    if (threadIdx.x == 0) base_s = 0;
    __syncthreads();
    for (int start = 0; start < NN; start += 1024) {
        int i = start + (int)threadIdx.x;
        int v = (i < NN) ? g_cnt[i] : 0;
        sdata[threadIdx.x] = v;
        __syncthreads();
        for (int off = 1; off < 1024; off <<= 1) {
            int t = ((int)threadIdx.x >= off) ? sdata[threadIdx.x - off] : 0;
            __syncthreads();
            sdata[threadIdx.x] += t;
            __syncthreads();
        }
        int incl = sdata[threadIdx.x];
        int total = sdata[1023];
        int base = base_s;
        if (i < NN) g_rowptr[i] = base + incl - v;
        __syncthreads();
        if (threadIdx.x == 0) base_s = base + total;
        __syncthreads();
    }
    if (threadIdx.x == 0) g_rowptr[NN] = base_s;
}
__global__ void cursor_kernel() {
    int i = blockIdx.x * blockDim.x + threadIdx.x;
    if (i < NN) g_cursor[i] = g_rowptr[i];
}
__global__ void fill_kernel() {
    int e = blockIdx.x * blockDim.x + threadIdx.x;
    if (e < NE) {
        int pos = atomicAdd(&g_cursor[g_dst[e]], 1);
        g_ids[pos] = g_src[e];
    }
}

// ---------------- split-precision conversions ----------------
// A [M,K] fp32 -> A' [M,3K] bf16 : [hi | lo | hi]   (only needed for x)
__global__ void convA_kernel(const float* __restrict__ A, __nv_bfloat16* __restrict__ Ap,
                             int M, int K) {
    int idx = blockIdx.x * blockDim.x + threadIdx.x;
    if (idx >= M * K) return;
    int m = idx / K, k = idx - m * K;
    float a = A[idx];
    __nv_bfloat16 hi = __float2bfloat16(a);
    __nv_bfloat16 lo = __float2bfloat16(a - __bfloat162float(hi));
    size_t base = (size_t)m * 3 * K;
    Ap[base + k] = hi;
    Ap[base + K + k] = lo;
    Ap[base + 2 * K + k] = hi;
}
// W [K,256] fp32 -> W' [256,3K] bf16 K-major transposed : [hi | hi | lo]
__global__ void convW_kernel(const float* __restrict__ W, __nv_bfloat16* __restrict__ Wp, int K) {
    int idx = blockIdx.x * blockDim.x + threadIdx.x;
    if (idx >= K * 256) return;
    int k = idx >> 8, n = idx & 255;
    float a = W[idx];
    __nv_bfloat16 hi = __float2bfloat16(a);
    __nv_bfloat16 lo = __float2bfloat16(a - __bfloat162float(hi));
    size_t base = (size_t)n * 3 * K;
    Wp[base + k] = hi;
    Wp[base + K + k] = hi;
    Wp[base + 2 * K + k] = lo;
}

// ---------------- HMMA GEMM: C[M,256/512] = A'[M,Kp] x W'[Nrows,Kp]^T ----------------
// CTA tile 128(M) x 256(N), 8 warps as 2(m) x 4(n) -> warp tile 64x64.
// grid.x = column tile (selects 256-row slab of B and output buffer C0/C1).
#define BKH 64
#define TSTR 72                         // smem row stride in halves (144B, LDSM conflict-free)
#define A_HALVES (128 * TSTR)           // 9216 halves / buffer
#define B_HALVES (256 * TSTR)           // 18432 halves / buffer
#define SMEM_HALVES (2 * A_HALVES + 2 * B_HALVES)  // 55296 halves = 110592 B

__global__ __launch_bounds__(256) void hgemm_kernel(const __nv_bfloat16* __restrict__ A,
                                                    const __nv_bfloat16* __restrict__ B,
                                                    float* __restrict__ C0,
                                                    float* __restrict__ C1,
                                                    int M, int Kp) {
    extern __shared__ __nv_bfloat16 smh[];
    const int tid = threadIdx.x;
    const int lane = tid & 31;
    const int wid = tid >> 5;
    const int warp_m = (wid >> 2) * 64;   // 0,64
    const int warp_n = (wid & 3) * 64;    // 0,64,128,192
    const int colTile = blockIdx.x;
    const int rowTile = blockIdx.y;
    float* __restrict__ C = colTile ? C1 : C0;
    const __nv_bfloat16* __restrict__ Bt = B + (size_t)colTile * 256 * Kp;

    const uint32_t sbase = smem_u32(smh);

    float acc[4][8][4];
#pragma unroll
    for (int i = 0; i < 4; i++)
#pragma unroll
        for (int j = 0; j < 8; j++)
#pragma unroll
            for (int q = 0; q < 4; q++) acc[i][j][q] = 0.f;

    const int nCh = Kp >> 6;

    // ldmatrix per-lane coords
    const int aRow = warp_m + (lane & 15);
    const int aCol = (lane >> 4) << 3;
    const int bRow = warp_n + (lane & 7) + (((lane >> 4) & 1) << 3);
    const int bCol = ((lane >> 3) & 1) << 3;

    auto load_tile = [&](int c, int buf) {
        // A: 128 rows x 64 halves = 1024 x 16B, 4 per thread
#pragma unroll
        for (int i = 0; i < 4; i++) {
            int linear = i * 256 + tid;
            int row = linear >> 3;
            int c8 = (linear & 7) << 3;
            int grow = rowTile * 128 + row;
            int gsafe = grow < M ? grow : (M - 1);
            const __nv_bfloat16* src = A + (size_t)gsafe * Kp + c * BKH + c8;
            uint32_t dst = sbase + (uint32_t)(buf * A_HALVES + row * TSTR + c8) * 2;
            cp_async16(dst, src, grow < M ? 16 : 0);
        }
        // B: 256 rows x 64 halves = 2048 x 16B, 8 per thread
#pragma unroll
        for (int i = 0; i < 8; i++) {
            int linear = i * 256 + tid;
            int row = linear >> 3;
            int c8 = (linear & 7) << 3;
            const __nv_bfloat16* src = Bt + (size_t)row * Kp + c * BKH + c8;
            uint32_t dst = sbase + (uint32_t)(2 * A_HALVES + buf * B_HALVES + row * TSTR + c8) * 2;
            cp_async16(dst, src, 16);
        }
        CP_COMMIT();
    };

    load_tile(0, 0);

    for (int c = 0; c < nCh; c++) {
        CP_WAIT0();
        __syncthreads();
        if (c + 1 < nCh) load_tile(c + 1, (c + 1) & 1);

        const int buf = c & 1;
        const uint32_t baseA = sbase + (uint32_t)(buf * A_HALVES) * 2;
        const uint32_t baseB = sbase + (uint32_t)(2 * A_HALVES + buf * B_HALVES) * 2;
#pragma unroll
        for (int ks = 0; ks < 4; ks++) {
            uint32_t aF[4][4];
#pragma unroll
            for (int mi = 0; mi < 4; mi++) {
                uint32_t addr = baseA + (uint32_t)((aRow + mi * 16) * TSTR + ks * 16 + aCol) * 2;
                asm volatile("ldmatrix.sync.aligned.m8n8.x4.shared.b16 {%0,%1,%2,%3}, [%4];"
                             : "=r"(aF[mi][0]), "=r"(aF[mi][1]), "=r"(aF[mi][2]), "=r"(aF[mi][3])
                             : "r"(addr));
            }
            uint32_t bF[4][4];
#pragma unroll
            for (int g = 0; g < 4; g++) {
                uint32_t addr = baseB + (uint32_t)((bRow + g * 16) * TSTR + ks * 16 + bCol) * 2;
                asm volatile("ldmatrix.sync.aligned.m8n8.x4.shared.b16 {%0,%1,%2,%3}, [%4];"
                             : "=r"(bF[g][0]), "=r"(bF[g][1]), "=r"(bF[g][2]), "=r"(bF[g][3])
                             : "r"(addr));
            }
#pragma unroll
            for (int mi = 0; mi < 4; mi++)
#pragma unroll
                for (int nj = 0; nj < 8; nj++) {
                    uint32_t b0 = bF[nj >> 1][(nj & 1) * 2];
                    uint32_t b1 = bF[nj >> 1][(nj & 1) * 2 + 1];
                    asm volatile(
                        "mma.sync.aligned.m16n8k16.row.col.f32.bf16.bf16.f32 "
                        "{%0,%1,%2,%3}, {%4,%5,%6,%7}, {%8,%9}, {%0,%1,%2,%3};"
                        : "+f"(acc[mi][nj][0]), "+f"(acc[mi][nj][1]),
                          "+f"(acc[mi][nj][2]), "+f"(acc[mi][nj][3])
                        : "r"(aF[mi][0]), "r"(aF[mi][1]), "r"(aF[mi][2]), "r"(aF[mi][3]),
                          "r"(b0), "r"(b1));
                }
        }
    }

    // epilogue
#pragma unroll
    for (int mi = 0; mi < 4; mi++) {
        int gr = rowTile * 128 + warp_m + mi * 16 + (lane >> 2);
        int gcBase = warp_n + (lane & 3) * 2;
#pragma unroll
        for (int nj = 0; nj < 8; nj++) {
            int gc = gcBase + nj * 8;
            if (gr < M)
                *(float2*)(C + (size_t)gr * 256 + gc) = make_float2(acc[mi][nj][0], acc[mi][nj][1]);
            if (gr + 8 < M)
                *(float2*)(C + (size_t)(gr + 8) * 256 + gc) = make_float2(acc[mi][nj][2], acc[mi][nj][3]);
        }
    }
}

// ---------------- per-node attention logits ----------------
__global__ void alphas_kernel(const float* __restrict__ h,
                              const float* __restrict__ avs,
                              const float* __restrict__ avd) {
    int node = blockIdx.x * (blockDim.x >> 5) + (threadIdx.x >> 5);
    int lane = threadIdx.x & 31;
    if (node >= NN) return;
    const float4* hr = (const float4*)(h + (size_t)node * HIDF);
    const float4* s4 = (const float4*)avs;
    const float4* d4 = (const float4*)avd;
    float ss = 0.f, sd = 0.f;
#pragma unroll
    for (int k = 0; k < 2; k++) {
        int c = lane + k * 32;
        float4 hv = hr[c];
        float4 a = s4[c];
        float4 b = d4[c];
        ss += hv.x * a.x + hv.y * a.y + hv.z * a.z + hv.w * a.w;
        sd += hv.x * b.x + hv.y * b.y + hv.z * b.z + hv.w * b.w;
    }
#pragma unroll
    for (int o = 16; o; o >>= 1) {
        ss += __shfl_xor_sync(0xffffffffu, ss, o);
        sd += __shfl_xor_sync(0xffffffffu, sd, o);
    }
    if (lane == 0) {
        g_as[node] = ss;
        g_ad[node] = sd;
    }
}

// ---------------- split-bf16 float4 store helper ----------------
__device__ __forceinline__ void store_split4(__nv_bfloat16* p_hi, __nv_bfloat16* p_lo,
                                             __nv_bfloat16* p_hi2, float4 v) {
    __nv_bfloat16 h0 = __float2bfloat16(v.x), h1 = __float2bfloat16(v.y);
    __nv_bfloat16 h2 = __float2bfloat16(v.z), h3 = __float2bfloat16(v.w);
    __nv_bfloat16 l0 = __float2bfloat16(v.x - __bfloat162float(h0));
    __nv_bfloat16 l1 = __float2bfloat16(v.y - __bfloat162float(h1));
    __nv_bfloat16 l2 = __float2bfloat16(v.z - __bfloat162float(h2));
    __nv_bfloat16 l3 = __float2bfloat16(v.w - __bfloat162float(h3));
    ushort4 hs = make_ushort4(__bfloat16_as_ushort(h0), __bfloat16_as_ushort(h1),
                              __bfloat16_as_ushort(h2), __bfloat16_as_ushort(h3));
    ushort4 ls = make_ushort4(__bfloat16_as_ushort(l0), __bfloat16_as_ushort(l1),
                              __bfloat16_as_ushort(l2), __bfloat16_as_ushort(l3));
    *(ushort4*)p_hi = hs;
    *(ushort4*)p_lo = ls;
    *(ushort4*)p_hi2 = hs;
}

// ---------------- single-pass segment softmax + aggregation (split-bf16 output) ----------
// softmax is shift-invariant; logits are small (|e| <~ 12 << 88) so no max pass needed.
// out = (e_self*h[node] + sum_j e_j*h[src_j]) / (e_self + sum_j e_j)
__global__ void aggregate_kernel(const float* __restrict__ h,
                                 const float* __restrict__ bias,
                                 __nv_bfloat16* __restrict__ Ap,
                                 int do_relu) {
    int node = blockIdx.x * (blockDim.x >> 5) + (threadIdx.x >> 5);
    int lane = threadIdx.x & 31;
    if (node >= NN) return;
    int beg = g_rowptr[node];
    int end = g_rowptr[node + 1];
    float add = g_ad[node];
    float e_self = __expf(lrelu(g_as[node] + add));

    int c0 = lane;
    int c1 = lane + 32;
    const float4* hp = (const float4*)(h + (size_t)node * HIDF);
    float4 v0 = hp[c0], v1 = hp[c1];
    float s = e_self;
    float4 acc0 = make_float4(e_self * v0.x, e_self * v0.y, e_self * v0.z, e_self * v0.w);
    float4 acc1 = make_float4(e_self * v1.x, e_self * v1.y, e_self * v1.z, e_self * v1.w);

    // software-pipelined gather: prefetch next edge's weight + feature row
    int j = beg;
    float wj = 0.f;
    float4 u0 = make_float4(0, 0, 0, 0), u1 = make_float4(0, 0, 0, 0);
    if (j < end) {
        int sj = g_ids[j];
        wj = __expf(lrelu(g_as[sj] + add));
        const float4* hq = (const float4*)(h + (size_t)sj * HIDF);
        u0 = hq[c0];
        u1 = hq[c1];
    }
    while (j < end) {
        int jn = j + 1;
        float wn = 0.f;
        float4 n0 = make_float4(0, 0, 0, 0), n1 = make_float4(0, 0, 0, 0);
        if (jn < end) {
            int sjn = g_ids[jn];
            wn = __expf(lrelu(g_as[sjn] + add));
            const float4* hn = (const float4*)(h + (size_t)sjn * HIDF);
            n0 = hn[c0];
            n1 = hn[c1];
        }
        acc0.x += wj * u0.x; acc0.y += wj * u0.y; acc0.z += wj * u0.z; acc0.w += wj * u0.w;
        acc1.x += wj * u1.x; acc1.y += wj * u1.y; acc1.z += wj * u1.z; acc1.w += wj * u1.w;
        s += wj;
        wj = wn; u0 = n0; u1 = n1; j = jn;
    }

    float inv = 1.0f / s;
    const float4* b4 = (const float4*)bias;
    float4 b0 = b4[c0], b1 = b4[c1];
    acc0.x = acc0.x * inv + b0.x; acc0.y = acc0.y * inv + b0.y;
    acc0.z = acc0.z * inv + b0.z; acc0.w = acc0.w * inv + b0.w;
    acc1.x = acc1.x * inv + b1.x; acc1.y = acc1.y * inv + b1.y;
    acc1.z = acc1.z * inv + b1.z; acc1.w = acc1.w * inv + b1.w;
    if (do_relu) {
        acc0.x = fmaxf(acc0.x, 0.f); acc0.y = fmaxf(acc0.y, 0.f);
        acc0.z = fmaxf(acc0.z, 0.f); acc0.w = fmaxf(acc0.w, 0.f);
        acc1.x = fmaxf(acc1.x, 0.f); acc1.y = fmaxf(acc1.y, 0.f);
        acc1.z = fmaxf(acc1.z, 0.f); acc1.w = fmaxf(acc1.w, 0.f);
    }
    // write split-bf16 [hi | lo | hi] rows of width 768
    __nv_bfloat16* row = Ap + (size_t)node * 768;
    store_split4(row + 4 * lane, row + 256 + 4 * lane, row + 512 + 4 * lane, acc0);
    store_split4(row + 128 + 4 * lane, row + 384 + 4 * lane, row + 640 + 4 * lane, acc1);
}

// ---------------- edge head: out[e] = P1[src[e]] + P2[dst[e]] + lin_b ----------------
__global__ void edge_out_kernel(const float* __restrict__ P1,
                                const float* __restrict__ P2,
                                const float* __restrict__ lin_b,
                                float* __restrict__ out) {
    int e = blockIdx.x * (blockDim.x >> 5) + (threadIdx.x >> 5);
    int lane = threadIdx.x & 31;
    if (e >= NE) return;
    int s = g_src[e];
    int d = g_dst[e];
    const float4* p1 = (const float4*)(P1 + (size_t)s * HIDF);
    const float4* p2 = (const float4*)(P2 + (size_t)d * HIDF);
    const float4* b4 = (const float4*)lin_b;
    float4* o4 = (float4*)(out + (size_t)e * HIDF);
#pragma unroll
    for (int k = 0; k < 2; k++) {
        int c = lane + k * 32;
        float4 a = p1[c];
        float4 b = p2[c];
        float4 bb = b4[c];
        float4 r = make_float4(a.x + b.x + bb.x, a.y + b.y + bb.y,
                               a.z + b.z + bb.z, a.w + b.w + bb.w);
        // streaming store: output is write-once, keep L2 for the gather tables
        asm volatile("st.global.cs.v4.f32 [%0], {%1,%2,%3,%4};"
                     :: "l"(o4 + c), "f"(r.x), "f"(r.y), "f"(r.z), "f"(r.w) : "memory");
    }
}

// ---------------- host ----------------
extern "C" void kernel_launch(void* const* d_in, const int* in_sizes, int n_in,
                              void* d_out, int out_size) {
    const float* x      = (const float*)d_in[0];
    const void*  eidx   = d_in[1];
    const float* W1     = (const float*)d_in[2];
    const float* a1_src = (const float*)d_in[3];
    const float* a1_dst = (const float*)d_in[4];
    const float* b1     = (const float*)d_in[5];
    const float* W2     = (const float*)d_in[6];
    const float* a2_src = (const float*)d_in[7];
    const float* a2_dst = (const float*)d_in[8];
    const float* b2     = (const float*)d_in[9];
    const float* lin_W  = (const float*)d_in[10];
    const float* lin_b  = (const float*)d_in[11];
    float* out = (float*)d_out;

    float *bufA, *bufB;
    __nv_bfloat16 *abf, *wbf;
    cudaGetSymbolAddress((void**)&bufA, g_bufA);
    cudaGetSymbolAddress((void**)&bufB, g_bufB);
    cudaGetSymbolAddress((void**)&abf, g_abf);
    cudaGetSymbolAddress((void**)&wbf, g_wbf);

    const int SMEM_BYTES = SMEM_HALVES * 2;
    cudaFuncSetAttribute(hgemm_kernel, cudaFuncAttributeMaxDynamicSharedMemorySize, SMEM_BYTES);

    const int TPB = 256;
    const int edgeBlocks = (NE + TPB - 1) / TPB;
    const int nodeBlocks = (NN + TPB - 1) / TPB;
    const int warpNodeBlocks = (NN + 7) / 8;
    const int warpEdgeBlocks = (NE + 7) / 8;
    const int gemmBlocks = (NN + 127) / 128;
    dim3 g1(1, gemmBlocks);
    dim3 g2(2, gemmBlocks);

    // ordered so launch #6 (profiled) is the first hgemm
    convA_kernel<<<(NN * 128 + TPB - 1) / TPB, TPB>>>(x, abf, NN, 128);             // 1
    convW_kernel<<<(128 * 256 + TPB - 1) / TPB, TPB>>>(W1, wbf, 128);               // 2
    detect_kernel<<<1, 256>>>((const int*)eidx);                                    // 3
    convert_kernel<<<edgeBlocks, TPB>>>(eidx);                                      // 4
    zero_cnt_kernel<<<nodeBlocks, TPB>>>();                                         // 5
    hgemm_kernel<<<g1, 256, SMEM_BYTES>>>(abf, wbf, bufA, bufA, NN, 384);           // 6 <- ncu
    count_kernel<<<edgeBlocks, TPB>>>();                                            // 7
    scan_kernel<<<1, 1024>>>();                                                     // 8
    cursor_kernel<<<nodeBlocks, TPB>>>();                                           // 9
    fill_kernel<<<edgeBlocks, TPB>>>();                                             // 10
    alphas_kernel<<<warpNodeBlocks, TPB>>>(bufA, a1_src, a1_dst);                   // 11
    aggregate_kernel<<<warpNodeBlocks, TPB>>>(bufA, b1, abf, 1);                    // 12

    convW_kernel<<<(256 * 256 + TPB - 1) / TPB, TPB>>>(W2, wbf, 256);               // 13
    hgemm_kernel<<<g1, 256, SMEM_BYTES>>>(abf, wbf, bufB, bufB, NN, 768);           // 14
    alphas_kernel<<<warpNodeBlocks, TPB>>>(bufB, a2_src, a2_dst);                   // 15
    aggregate_kernel<<<warpNodeBlocks, TPB>>>(bufB, b2, abf, 0);                    // 16

    // fused edge head: W' has 512 rows (P1 slab | P2 slab); one GEMM launch covers both
    convW_kernel<<<(256 * 256 + TPB - 1) / TPB, TPB>>>(lin_W, wbf, 256);            // 17
    convW_kernel<<<(256 * 256 + TPB - 1) / TPB, TPB>>>(lin_W + 256 * 256,
                                                       wbf + (size_t)256 * 768, 256); // 18
    hgemm_kernel<<<g2, 256, SMEM_BYTES>>>(abf, wbf, bufA, bufB, NN, 768);           // 19
    edge_out_kernel<<<warpEdgeBlocks, TPB>>>(bufA, bufB, lin_b, out);               // 20
}

// round 17
// speedup vs baseline: 1.6300x; 1.0604x over previous
#include <cuda_runtime.h>
#include <cuda_bf16.h>
#include <cstdint>
#include <math.h>

#define NN 50000
#define NE 500000
#define HIDF 256
#define NEG_SLOPE 0.2f

// ---------------- scratch (no allocation allowed) ----------------
__device__ __align__(256) float g_bufA[(size_t)NN * HIDF];
__device__ __align__(256) float g_bufB[(size_t)NN * HIDF];
__device__ __align__(256) __nv_bfloat16 g_abf[(size_t)NN * 768];   // A' split bf16 (max K'=768)
__device__ __align__(256) __nv_bfloat16 g_wbf[(size_t)512 * 768];  // W' split bf16 (head: 512 rows)
__device__ int g_src[NE];
__device__ int g_dst[NE];
__device__ int g_cnt[NN];
__device__ int g_rowptr[NN + 1];
__device__ int g_cursor[NN];
__device__ int g_ids[NE];   // SRC node id of CSR-sorted edge
__device__ int g_eid[NE];   // original edge id of CSR-sorted edge
__device__ float g_as[NN];
__device__ float g_ad[NN];
__device__ int g_is64;

// ---------------- helpers ----------------
__device__ __forceinline__ uint32_t smem_u32(const void* p) {
    uint32_t a;
    asm("{ .reg .u64 t; cvta.to.shared.u64 t, %1; cvt.u32.u64 %0, t; }" : "=r"(a) : "l"(p));
    return a;
}
__device__ __forceinline__ void cp_async16(uint32_t dst, const void* src, int sz) {
    asm volatile("cp.async.cg.shared.global [%0], [%1], 16, %2;" :: "r"(dst), "l"(src), "r"(sz) : "memory");
}
#define CP_COMMIT() asm volatile("cp.async.commit_group;" ::: "memory")
#define CP_WAIT0()  asm volatile("cp.async.wait_group 0;" ::: "memory")

__device__ __forceinline__ float lrelu(float e) { return e > 0.f ? e : NEG_SLOPE * e; }

// ---------------- edge index dtype detection + normalize ----------------
__global__ void detect_kernel(const int* __restrict__ w) {
    __shared__ int sh[256];
    int nz = 0;
    for (int i = 1 + 2 * (int)threadIdx.x; i < 1000000; i += 2 * (int)blockDim.x)
        nz += (w[i] != 0);
    sh[threadIdx.x] = nz;
    __syncthreads();
    for (int off = 128; off; off >>= 1) {
        if ((int)threadIdx.x < off) sh[threadIdx.x] += sh[threadIdx.x + off];
        __syncthreads();
    }
    if (threadIdx.x == 0) g_is64 = (sh[0] == 0) ? 1 : 0;
}

__global__ void convert_kernel(const void* __restrict__ ei) {
    int e = blockIdx.x * blockDim.x + threadIdx.x;
    if (e >= NE) return;
    if (g_is64) {
        const long long* p = (const long long*)ei;
        g_src[e] = (int)p[e];
        g_dst[e] = (int)p[NE + e];
    } else {
        const int* p = (const int*)ei;
        g_src[e] = p[e];
        g_dst[e] = p[NE + e];
    }
}

// ---------------- CSR build (sorted by dst, payload = src id + edge id) ----------------
__global__ void zero_cnt_kernel() {
    int i = blockIdx.x * blockDim.x + threadIdx.x;
    if (i < NN) g_cnt[i] = 0;
}
__global__ void count_kernel() {
    int e = blockIdx.x * blockDim.x + threadIdx.x;
    if (e < NE) atomicAdd(&g_cnt[g_dst[e]], 1);
}
__global__ void scan_kernel() {
    __shared__ int sdata[1024];
    __shared__ int base_s;
    if (threadIdx.x == 0) base_s = 0;
    __syncthreads();
    for (int start = 0; start < NN; start += 1024) {
        int i = start + (int)threadIdx.x;
        int v = (i < NN) ? g_cnt[i] : 0;
        sdata[threadIdx.x] = v;
        __syncthreads();
        for (int off = 1; off < 1024; off <<= 1) {
            int t = ((int)threadIdx.x >= off) ? sdata[threadIdx.x - off] : 0;
            __syncthreads();
            sdata[threadIdx.x] += t;
            __syncthreads();
        }
        int incl = sdata[threadIdx.x];
        int total = sdata[1023];
        int base = base_s;
        if (i < NN) g_rowptr[i] = base + incl - v;
        __syncthreads();
        if (threadIdx.x == 0) base_s = base + total;
        __syncthreads();
    }
    if (threadIdx.x == 0) g_rowptr[NN] = base_s;
}
__global__ void cursor_kernel() {
    int i = blockIdx.x * blockDim.x + threadIdx.x;
    if (i < NN) g_cursor[i] = g_rowptr[i];
}
__global__ void fill_kernel() {
    int e = blockIdx.x * blockDim.x + threadIdx.x;
    if (e < NE) {
        int pos = atomicAdd(&g_cursor[g_dst[e]], 1);
        g_ids[pos] = g_src[e];
        g_eid[pos] = e;
    }
}

// ---------------- split-precision conversions ----------------
// A [M,K] fp32 -> A' [M,3K] bf16 : [hi | lo | hi]   (only needed for x)
__global__ void convA_kernel(const float* __restrict__ A, __nv_bfloat16* __restrict__ Ap,
                             int M, int K) {
    int idx = blockIdx.x * blockDim.x + threadIdx.x;
    if (idx >= M * K) return;
    int m = idx / K, k = idx - m * K;
    float a = A[idx];
    __nv_bfloat16 hi = __float2bfloat16(a);
    __nv_bfloat16 lo = __float2bfloat16(a - __bfloat162float(hi));
    size_t base = (size_t)m * 3 * K;
    Ap[base + k] = hi;
    Ap[base + K + k] = lo;
    Ap[base + 2 * K + k] = hi;
}
// W [K,256] fp32 -> W' [256,3K] bf16 K-major transposed : [hi | hi | lo]
__global__ void convW_kernel(const float* __restrict__ W, __nv_bfloat16* __restrict__ Wp, int K) {
    int idx = blockIdx.x * blockDim.x + threadIdx.x;
    if (idx >= K * 256) return;
    int k = idx >> 8, n = idx & 255;
    float a = W[idx];
    __nv_bfloat16 hi = __float2bfloat16(a);
    __nv_bfloat16 lo = __float2bfloat16(a - __bfloat162float(hi));
    size_t base = (size_t)n * 3 * K;
    Wp[base + k] = hi;
    Wp[base + K + k] = hi;
    Wp[base + 2 * K + k] = lo;
}

// ---------------- HMMA GEMM: C[M,256/512] = A'[M,Kp] x W'[Nrows,Kp]^T ----------------
// CTA tile 128(M) x 256(N), 8 warps as 2(m) x 4(n) -> warp tile 64x64.
// grid.x = column tile (selects 256-row slab of B and output buffer C0/C1).
#define BKH 64
#define TSTR 72                         // smem row stride in halves (144B, LDSM conflict-free)
#define A_HALVES (128 * TSTR)           // 9216 halves / buffer
#define B_HALVES (256 * TSTR)           // 18432 halves / buffer
#define SMEM_HALVES (2 * A_HALVES + 2 * B_HALVES)  // 55296 halves = 110592 B

__global__ __launch_bounds__(256) void hgemm_kernel(const __nv_bfloat16* __restrict__ A,
                                                    const __nv_bfloat16* __restrict__ B,
                                                    float* __restrict__ C0,
                                                    float* __restrict__ C1,
                                                    int M, int Kp) {
    extern __shared__ __nv_bfloat16 smh[];
    const int tid = threadIdx.x;
    const int lane = tid & 31;
    const int wid = tid >> 5;
    const int warp_m = (wid >> 2) * 64;   // 0,64
    const int warp_n = (wid & 3) * 64;    // 0,64,128,192
    const int colTile = blockIdx.x;
    const int rowTile = blockIdx.y;
    float* __restrict__ C = colTile ? C1 : C0;
    const __nv_bfloat16* __restrict__ Bt = B + (size_t)colTile * 256 * Kp;

    const uint32_t sbase = smem_u32(smh);

    float acc[4][8][4];
#pragma unroll
    for (int i = 0; i < 4; i++)
#pragma unroll
        for (int j = 0; j < 8; j++)
#pragma unroll
            for (int q = 0; q < 4; q++) acc[i][j][q] = 0.f;

    const int nCh = Kp >> 6;

    // ldmatrix per-lane coords
    const int aRow = warp_m + (lane & 15);
    const int aCol = (lane >> 4) << 3;
    const int bRow = warp_n + (lane & 7) + (((lane >> 4) & 1) << 3);
    const int bCol = ((lane >> 3) & 1) << 3;

    auto load_tile = [&](int c, int buf) {
        // A: 128 rows x 64 halves = 1024 x 16B, 4 per thread
#pragma unroll
        for (int i = 0; i < 4; i++) {
            int linear = i * 256 + tid;
            int row = linear >> 3;
            int c8 = (linear & 7) << 3;
            int grow = rowTile * 128 + row;
            int gsafe = grow < M ? grow : (M - 1);
            const __nv_bfloat16* src = A + (size_t)gsafe * Kp + c * BKH + c8;
            uint32_t dst = sbase + (uint32_t)(buf * A_HALVES + row * TSTR + c8) * 2;
            cp_async16(dst, src, grow < M ? 16 : 0);
        }
        // B: 256 rows x 64 halves = 2048 x 16B, 8 per thread
#pragma unroll
        for (int i = 0; i < 8; i++) {
            int linear = i * 256 + tid;
            int row = linear >> 3;
            int c8 = (linear & 7) << 3;
            const __nv_bfloat16* src = Bt + (size_t)row * Kp + c * BKH + c8;
            uint32_t dst = sbase + (uint32_t)(2 * A_HALVES + buf * B_HALVES + row * TSTR + c8) * 2;
            cp_async16(dst, src, 16);
        }
        CP_COMMIT();
    };

    load_tile(0, 0);

    for (int c = 0; c < nCh; c++) {
        CP_WAIT0();
        __syncthreads();
        if (c + 1 < nCh) load_tile(c + 1, (c + 1) & 1);

        const int buf = c & 1;
        const uint32_t baseA = sbase + (uint32_t)(buf * A_HALVES) * 2;
        const uint32_t baseB = sbase + (uint32_t)(2 * A_HALVES + buf * B_HALVES) * 2;
#pragma unroll
        for (int ks = 0; ks < 4; ks++) {
            uint32_t aF[4][4];
#pragma unroll
            for (int mi = 0; mi < 4; mi++) {
                uint32_t addr = baseA + (uint32_t)((aRow + mi * 16) * TSTR + ks * 16 + aCol) * 2;
                asm volatile("ldmatrix.sync.aligned.m8n8.x4.shared.b16 {%0,%1,%2,%3}, [%4];"
                             : "=r"(aF[mi][0]), "=r"(aF[mi][1]), "=r"(aF[mi][2]), "=r"(aF[mi][3])
                             : "r"(addr));
            }
            uint32_t bF[4][4];
#pragma unroll
            for (int g = 0; g < 4; g++) {
                uint32_t addr = baseB + (uint32_t)((bRow + g * 16) * TSTR + ks * 16 + bCol) * 2;
                asm volatile("ldmatrix.sync.aligned.m8n8.x4.shared.b16 {%0,%1,%2,%3}, [%4];"
                             : "=r"(bF[g][0]), "=r"(bF[g][1]), "=r"(bF[g][2]), "=r"(bF[g][3])
                             : "r"(addr));
            }
#pragma unroll
            for (int mi = 0; mi < 4; mi++)
#pragma unroll
                for (int nj = 0; nj < 8; nj++) {
                    uint32_t b0 = bF[nj >> 1][(nj & 1) * 2];
                    uint32_t b1 = bF[nj >> 1][(nj & 1) * 2 + 1];
                    asm volatile(
                        "mma.sync.aligned.m16n8k16.row.col.f32.bf16.bf16.f32 "
                        "{%0,%1,%2,%3}, {%4,%5,%6,%7}, {%8,%9}, {%0,%1,%2,%3};"
                        : "+f"(acc[mi][nj][0]), "+f"(acc[mi][nj][1]),
                          "+f"(acc[mi][nj][2]), "+f"(acc[mi][nj][3])
                        : "r"(aF[mi][0]), "r"(aF[mi][1]), "r"(aF[mi][2]), "r"(aF[mi][3]),
                          "r"(b0), "r"(b1));
                }
        }
    }

    // epilogue
#pragma unroll
    for (int mi = 0; mi < 4; mi++) {
        int gr = rowTile * 128 + warp_m + mi * 16 + (lane >> 2);
        int gcBase = warp_n + (lane & 3) * 2;
#pragma unroll
        for (int nj = 0; nj < 8; nj++) {
            int gc = gcBase + nj * 8;
            if (gr < M)
                *(float2*)(C + (size_t)gr * 256 + gc) = make_float2(acc[mi][nj][0], acc[mi][nj][1]);
            if (gr + 8 < M)
                *(float2*)(C + (size_t)(gr + 8) * 256 + gc) = make_float2(acc[mi][nj][2], acc[mi][nj][3]);
        }
    }
}

// ---------------- per-node attention logits ----------------
__global__ void alphas_kernel(const float* __restrict__ h,
                              const float* __restrict__ avs,
                              const float* __restrict__ avd) {
    int node = blockIdx.x * (blockDim.x >> 5) + (threadIdx.x >> 5);
    int lane = threadIdx.x & 31;
    if (node >= NN) return;
    const float4* hr = (const float4*)(h + (size_t)node * HIDF);
    const float4* s4 = (const float4*)avs;
    const float4* d4 = (const float4*)avd;
    float ss = 0.f, sd = 0.f;
#pragma unroll
    for (int k = 0; k < 2; k++) {
        int c = lane + k * 32;
        float4 hv = hr[c];
        float4 a = s4[c];
        float4 b = d4[c];
        ss += hv.x * a.x + hv.y * a.y + hv.z * a.z + hv.w * a.w;
        sd += hv.x * b.x + hv.y * b.y + hv.z * b.z + hv.w * b.w;
    }
#pragma unroll
    for (int o = 16; o; o >>= 1) {
        ss += __shfl_xor_sync(0xffffffffu, ss, o);
        sd += __shfl_xor_sync(0xffffffffu, sd, o);
    }
    if (lane == 0) {
        g_as[node] = ss;
        g_ad[node] = sd;
    }
}

// ---------------- split-bf16 float4 store helper ----------------
__device__ __forceinline__ void store_split4(__nv_bfloat16* p_hi, __nv_bfloat16* p_lo,
                                             __nv_bfloat16* p_hi2, float4 v) {
    __nv_bfloat16 h0 = __float2bfloat16(v.x), h1 = __float2bfloat16(v.y);
    __nv_bfloat16 h2 = __float2bfloat16(v.z), h3 = __float2bfloat16(v.w);
    __nv_bfloat16 l0 = __float2bfloat16(v.x - __bfloat162float(h0));
    __nv_bfloat16 l1 = __float2bfloat16(v.y - __bfloat162float(h1));
    __nv_bfloat16 l2 = __float2bfloat16(v.z - __bfloat162float(h2));
    __nv_bfloat16 l3 = __float2bfloat16(v.w - __bfloat162float(h3));
    ushort4 hs = make_ushort4(__bfloat16_as_ushort(h0), __bfloat16_as_ushort(h1),
                              __bfloat16_as_ushort(h2), __bfloat16_as_ushort(h3));
    ushort4 ls = make_ushort4(__bfloat16_as_ushort(l0), __bfloat16_as_ushort(l1),
                              __bfloat16_as_ushort(l2), __bfloat16_as_ushort(l3));
    *(ushort4*)p_hi = hs;
    *(ushort4*)p_lo = ls;
    *(ushort4*)p_hi2 = hs;
}

// ---------------- single-pass segment softmax + aggregation (split-bf16 output) ----------
// softmax is shift-invariant; logits are small (|e| <~ 12 << 88) so no max pass needed.
// out = (e_self*h[node] + sum_j e_j*h[src_j]) / (e_self + sum_j e_j)
__global__ void aggregate_kernel(const float* __restrict__ h,
                                 const float* __restrict__ bias,
                                 __nv_bfloat16* __restrict__ Ap,
                                 int do_relu) {
    int node = blockIdx.x * (blockDim.x >> 5) + (threadIdx.x >> 5);
    int lane = threadIdx.x & 31;
    if (node >= NN) return;
    int beg = g_rowptr[node];
    int end = g_rowptr[node + 1];
    float add = g_ad[node];
    float e_self = __expf(lrelu(g_as[node] + add));

    int c0 = lane;
    int c1 = lane + 32;
    const float4* hp = (const float4*)(h + (size_t)node * HIDF);
    float4 v0 = hp[c0], v1 = hp[c1];
    float s = e_self;
    float4 acc0 = make_float4(e_self * v0.x, e_self * v0.y, e_self * v0.z, e_self * v0.w);
    float4 acc1 = make_float4(e_self * v1.x, e_self * v1.y, e_self * v1.z, e_self * v1.w);

    // software-pipelined gather: prefetch next edge's weight + feature row
    int j = beg;
    float wj = 0.f;
    float4 u0 = make_float4(0, 0, 0, 0), u1 = make_float4(0, 0, 0, 0);
    if (j < end) {
        int sj = g_ids[j];
        wj = __expf(lrelu(g_as[sj] + add));
        const float4* hq = (const float4*)(h + (size_t)sj * HIDF);
        u0 = hq[c0];
        u1 = hq[c1];
    }
    while (j < end) {
        int jn = j + 1;
        float wn = 0.f;
        float4 n0 = make_float4(0, 0, 0, 0), n1 = make_float4(0, 0, 0, 0);
        if (jn < end) {
            int sjn = g_ids[jn];
            wn = __expf(lrelu(g_as[sjn] + add));
            const float4* hn = (const float4*)(h + (size_t)sjn * HIDF);
            n0 = hn[c0];
            n1 = hn[c1];
        }
        acc0.x += wj * u0.x; acc0.y += wj * u0.y; acc0.z += wj * u0.z; acc0.w += wj * u0.w;
        acc1.x += wj * u1.x; acc1.y += wj * u1.y; acc1.z += wj * u1.z; acc1.w += wj * u1.w;
        s += wj;
        wj = wn; u0 = n0; u1 = n1; j = jn;
    }

    float inv = 1.0f / s;
    const float4* b4 = (const float4*)bias;
    float4 b0 = b4[c0], b1 = b4[c1];
    acc0.x = acc0.x * inv + b0.x; acc0.y = acc0.y * inv + b0.y;
    acc0.z = acc0.z * inv + b0.z; acc0.w = acc0.w * inv + b0.w;
    acc1.x = acc1.x * inv + b1.x; acc1.y = acc1.y * inv + b1.y;
    acc1.z = acc1.z * inv + b1.z; acc1.w = acc1.w * inv + b1.w;
    if (do_relu) {
        acc0.x = fmaxf(acc0.x, 0.f); acc0.y = fmaxf(acc0.y, 0.f);
        acc0.z = fmaxf(acc0.z, 0.f); acc0.w = fmaxf(acc0.w, 0.f);
        acc1.x = fmaxf(acc1.x, 0.f); acc1.y = fmaxf(acc1.y, 0.f);
        acc1.z = fmaxf(acc1.z, 0.f); acc1.w = fmaxf(acc1.w, 0.f);
    }
    // write split-bf16 [hi | lo | hi] rows of width 768
    __nv_bfloat16* row = Ap + (size_t)node * 768;
    store_split4(row + 4 * lane, row + 256 + 4 * lane, row + 512 + 4 * lane, acc0);
    store_split4(row + 128 + 4 * lane, row + 384 + 4 * lane, row + 640 + 4 * lane, acc1);
}

// ---------------- CSR-ordered edge head: for node d, out[eid] = P1[src] + (P2[d]+lin_b) ----
__global__ void edge_out_csr_kernel(const float* __restrict__ P1,
                                    const float* __restrict__ P2,
                                    const float* __restrict__ lin_b,
                                    float* __restrict__ out) {
    int node = blockIdx.x * (blockDim.x >> 5) + (threadIdx.x >> 5);
    int lane = threadIdx.x & 31;
    if (node >= NN) return;
    int beg = g_rowptr[node];
    int end = g_rowptr[node + 1];
    if (beg == end) return;
    int c0 = lane;
    int c1 = lane + 32;
    const float4* p2 = (const float4*)(P2 + (size_t)node * HIDF);
    const float4* b4 = (const float4*)lin_b;
    float4 t0 = p2[c0], t1 = p2[c1];
    float4 bb0 = b4[c0], bb1 = b4[c1];
    float4 base0 = make_float4(t0.x + bb0.x, t0.y + bb0.y, t0.z + bb0.z, t0.w + bb0.w);
    float4 base1 = make_float4(t1.x + bb1.x, t1.y + bb1.y, t1.z + bb1.z, t1.w + bb1.w);

    for (int j = beg; j < end; j++) {
        int src = g_ids[j];
        int eid = g_eid[j];
        const float4* p1 = (const float4*)(P1 + (size_t)src * HIDF);
        float4 a0 = p1[c0], a1 = p1[c1];
        float4* o4 = (float4*)(out + (size_t)eid * HIDF);
        float4 r0 = make_float4(a0.x + base0.x, a0.y + base0.y, a0.z + base0.z, a0.w + base0.w);
        float4 r1 = make_float4(a1.x + base1.x, a1.y + base1.y, a1.z + base1.z, a1.w + base1.w);
        asm volatile("st.global.cs.v4.f32 [%0], {%1,%2,%3,%4};"
                     :: "l"(o4 + c0), "f"(r0.x), "f"(r0.y), "f"(r0.z), "f"(r0.w) : "memory");
        asm volatile("st.global.cs.v4.f32 [%0], {%1,%2,%3,%4};"
                     :: "l"(o4 + c1), "f"(r1.x), "f"(r1.y), "f"(r1.z), "f"(r1.w) : "memory");
    }
}

// ---------------- host ----------------
extern "C" void kernel_launch(void* const* d_in, const int* in_sizes, int n_in,
                              void* d_out, int out_size) {
    const float* x      = (const float*)d_in[0];
    const void*  eidx   = d_in[1];
    const float* W1     = (const float*)d_in[2];
    const float* a1_src = (const float*)d_in[3];
    const float* a1_dst = (const float*)d_in[4];
    const float* b1     = (const float*)d_in[5];
    const float* W2     = (const float*)d_in[6];
    const float* a2_src = (const float*)d_in[7];
    const float* a2_dst = (const float*)d_in[8];
    const float* b2     = (const float*)d_in[9];
    const float* lin_W  = (const float*)d_in[10];
    const float* lin_b  = (const float*)d_in[11];
    float* out = (float*)d_out;

    float *bufA, *bufB;
    __nv_bfloat16 *abf, *wbf;
    cudaGetSymbolAddress((void**)&bufA, g_bufA);
    cudaGetSymbolAddress((void**)&bufB, g_bufB);
    cudaGetSymbolAddress((void**)&abf, g_abf);
    cudaGetSymbolAddress((void**)&wbf, g_wbf);

    const int SMEM_BYTES = SMEM_HALVES * 2;
    cudaFuncSetAttribute(hgemm_kernel, cudaFuncAttributeMaxDynamicSharedMemorySize, SMEM_BYTES);

    const int TPB = 256;
    const int edgeBlocks = (NE + TPB - 1) / TPB;
    const int nodeBlocks = (NN + TPB - 1) / TPB;
    const int warpNodeBlocks = (NN + 7) / 8;
    const int gemmBlocks = (NN + 127) / 128;
    dim3 g1(1, gemmBlocks);
    dim3 g2(2, gemmBlocks);

    // ordered so my 4th launch (= ncu capture position) is the first hgemm
    convA_kernel<<<(NN * 128 + TPB - 1) / TPB, TPB>>>(x, abf, NN, 128);             // 1
    convW_kernel<<<(128 * 256 + TPB - 1) / TPB, TPB>>>(W1, wbf, 128);               // 2
    detect_kernel<<<1, 256>>>((const int*)eidx);                                    // 3
    hgemm_kernel<<<g1, 256, SMEM_BYTES>>>(abf, wbf, bufA, bufA, NN, 384);           // 4 <- ncu
    convert_kernel<<<edgeBlocks, TPB>>>(eidx);                                      // 5
    zero_cnt_kernel<<<nodeBlocks, TPB>>>();                                         // 6
    count_kernel<<<edgeBlocks, TPB>>>();                                            // 7
    scan_kernel<<<1, 1024>>>();                                                     // 8
    cursor_kernel<<<nodeBlocks, TPB>>>();                                           // 9
    fill_kernel<<<edgeBlocks, TPB>>>();                                             // 10
    alphas_kernel<<<warpNodeBlocks, TPB>>>(bufA, a1_src, a1_dst);                   // 11
    aggregate_kernel<<<warpNodeBlocks, TPB>>>(bufA, b1, abf, 1);                    // 12

    convW_kernel<<<(256 * 256 + TPB - 1) / TPB, TPB>>>(W2, wbf, 256);               // 13
    hgemm_kernel<<<g1, 256, SMEM_BYTES>>>(abf, wbf, bufB, bufB, NN, 768);           // 14
    alphas_kernel<<<warpNodeBlocks, TPB>>>(bufB, a2_src, a2_dst);                   // 15
    aggregate_kernel<<<warpNodeBlocks, TPB>>>(bufB, b2, abf, 0);                    // 16

    // fused edge head: W' has 512 rows (P1 slab | P2 slab); one GEMM launch covers both
    convW_kernel<<<(256 * 256 + TPB - 1) / TPB, TPB>>>(lin_W, wbf, 256);            // 17
    convW_kernel<<<(256 * 256 + TPB - 1) / TPB, TPB>>>(lin_W + 256 * 256,
                                                       wbf + (size_t)256 * 768, 256); // 18
    hgemm_kernel<<<g2, 256, SMEM_BYTES>>>(abf, wbf, bufA, bufB, NN, 768);           // 19
    edge_out_csr_kernel<<<warpNodeBlocks, TPB>>>(bufA, bufB, lin_b, out);           // 20
}